// round 2
// baseline (speedup 1.0000x reference)
#include <cuda_runtime.h>

typedef unsigned long long ull;

#define Bsz 8
#define FD 1024
#define NN 65536            // N*N per batch
#define BNN (Bsz*NN)        // 524288
#define Ksel 39321          // int(0.6 * 65536)
#define M_TOT 2048          // B*N

// ---------------- scratch ----------------
__device__ float    g_pp[M_TOT * 512];     // [m][0:256)=pr+b1, [256:512)=pc
__device__ float    g_e[BNN];              // unnormalized exp
__device__ unsigned g_maxkey[Bsz];
__device__ float    g_inv_denom[Bsz];
__device__ float    g_part[Bsz * 16];
__device__ float    g_thr[Bsz];
__device__ float    g_cpart[Bsz * 16];
__device__ float    g_inv_csum[Bsz];

// ---------------- f32x2 helpers ----------------
__device__ __forceinline__ ull fpack(float lo, float hi) {
    ull r; asm("mov.b64 %0, {%1, %2};" : "=l"(r) : "f"(lo), "f"(hi)); return r;
}
__device__ __forceinline__ void funpack(ull v, float &lo, float &hi) {
    asm("mov.b64 {%0, %1}, %2;" : "=f"(lo), "=f"(hi) : "l"(v));
}
#define FMA2(d, a, b, c) asm("fma.rn.f32x2 %0, %1, %2, %3;" : "=l"(d) : "l"(a), "l"(b), "l"(c))
#define ADD2(d, a, b)    asm("add.rn.f32x2 %0, %1, %2;"     : "=l"(d) : "l"(a), "l"(b))

// monotone float<->uint encoding
__device__ __forceinline__ unsigned encf(float f) {
    unsigned u = __float_as_uint(f);
    return (u & 0x80000000u) ? ~u : (u | 0x80000000u);
}
__device__ __forceinline__ float decf(unsigned u) {
    unsigned v = (u & 0x80000000u) ? (u ^ 0x80000000u) : ~u;
    return __uint_as_float(v);
}

__global__ void init_kernel() {
    if (threadIdx.x < Bsz) g_maxkey[threadIdx.x] = 0u;
}

// ---------------- 1) GEMM (f32x2): C[m][j] = sum_f x[m][f]*Bmat[j][f] ----------------
// Bmat[j][f] = W1[(j&255)][(j>>8)*1024 + f]; b1 folded into cols<256.
// 128x64 tile, 256 threads, 8x4 per thread. A stored duplicated in smem so
// {a,a} pairs load directly; B pairs are natural.
__global__ __launch_bounds__(256) void gemm_kernel(
    const float* __restrict__ x, const float* __restrict__ W1, const float* __restrict__ b1)
{
    __shared__ float Asd[16][260];   // duplicated: Asd[k][2i]=Asd[k][2i+1]=A[i]
    __shared__ float Bs[16][68];
    const int tid = threadIdx.x;
    const int j0 = blockIdx.x << 6;
    const int m0 = blockIdx.y << 7;
    const int tx = tid & 15;          // cols 4tx..4tx+3
    const int ty = tid >> 4;          // rows 8ty..8ty+7
    const int ar0 = tid >> 2;         // 0..63 (+64 second half)
    const int ac4 = (tid & 3) << 2;
    const int bj  = tid >> 2;
    const int bc4 = (tid & 3) << 2;
    const int gj = j0 + bj;
    const float* wrow = W1 + (gj & 255) * 2048 + (gj >> 8) * 1024;
    const float* arow0 = x + (m0 + ar0) * 1024 + ac4;
    const float* arow1 = arow0 + 64 * 1024;

    ull acc[8][2];
    #pragma unroll
    for (int i = 0; i < 8; i++) { acc[i][0] = 0ull; acc[i][1] = 0ull; }

    float4 pa0 = *(const float4*)(arow0);
    float4 pa1 = *(const float4*)(arow1);
    float4 pb  = *(const float4*)(wrow + bc4);

    for (int k0 = 0; k0 < FD; k0 += 16) {
        __syncthreads();
        {
            float va[4] = {pa0.x, pa0.y, pa0.z, pa0.w};
            float vb[4] = {pa1.x, pa1.y, pa1.z, pa1.w};
            float vc[4] = {pb.x,  pb.y,  pb.z,  pb.w};
            #pragma unroll
            for (int d = 0; d < 4; d++) {
                *(float2*)&Asd[ac4 + d][2 * ar0]        = make_float2(va[d], va[d]);
                *(float2*)&Asd[ac4 + d][2 * (64 + ar0)] = make_float2(vb[d], vb[d]);
                Bs[bc4 + d][bj] = vc[d];
            }
        }
        __syncthreads();
        if (k0 + 16 < FD) {
            pa0 = *(const float4*)(arow0 + k0 + 16);
            pa1 = *(const float4*)(arow1 + k0 + 16);
            pb  = *(const float4*)(wrow + k0 + 16 + bc4);
        }
        #pragma unroll
        for (int k = 0; k < 16; k++) {
            float4 a01 = *(float4*)&Asd[k][16 * ty];
            float4 a23 = *(float4*)&Asd[k][16 * ty + 4];
            float4 a45 = *(float4*)&Asd[k][16 * ty + 8];
            float4 a67 = *(float4*)&Asd[k][16 * ty + 12];
            float4 b4  = *(float4*)&Bs[k][4 * tx];
            ull b01 = ((ull*)&b4)[0];
            ull b23 = ((ull*)&b4)[1];
            ull ad[8];
            ad[0] = ((ull*)&a01)[0]; ad[1] = ((ull*)&a01)[1];
            ad[2] = ((ull*)&a23)[0]; ad[3] = ((ull*)&a23)[1];
            ad[4] = ((ull*)&a45)[0]; ad[5] = ((ull*)&a45)[1];
            ad[6] = ((ull*)&a67)[0]; ad[7] = ((ull*)&a67)[1];
            #pragma unroll
            for (int i = 0; i < 8; i++) {
                FMA2(acc[i][0], ad[i], b01, acc[i][0]);
                FMA2(acc[i][1], ad[i], b23, acc[i][1]);
            }
        }
    }
    // epilogue
    float bias[4];
    #pragma unroll
    for (int jj = 0; jj < 4; jj++) {
        int col = j0 + 4 * tx + jj;
        bias[jj] = (col < 256) ? b1[col] : 0.f;
    }
    #pragma unroll
    for (int i = 0; i < 8; i++) {
        int m = m0 + 8 * ty + i;
        float c0, c1, c2, c3;
        funpack(acc[i][0], c0, c1);
        funpack(acc[i][1], c2, c3);
        *(float4*)(g_pp + m * 512 + j0 + 4 * tx) =
            make_float4(c0 + bias[0], c1 + bias[1], c2 + bias[2], c3 + bias[3]);
    }
}

// ---------------- 2) edge (f32x2): edge[b,i,j] = sum_h relu(pr+pc)*w2 + b2 ----------------
// Pair along j: c pairs natural from transposed smem, a duplicated, w duplicated.
__global__ __launch_bounds__(256) void edge_kernel(
    const float* __restrict__ W2, const float* __restrict__ b2, float* __restrict__ out_edge)
{
    __shared__ float adup[32][132];  // adup[h][2i]=adup[h][2i+1]=pr[i0b+i][hc+h]
    __shared__ float pcT[32][68];    // pcT[h][j] = pc[j0b+j][hc+h]
    __shared__ float2 wd[32];
    __shared__ float redbuf[8];
    const int b   = blockIdx.z;
    const int i0b = blockIdx.y << 6;
    const int j0b = blockIdx.x << 6;
    const int tid = threadIdx.x;
    const int tx = tid & 15;         // cols 4tx..4tx+3
    const int ty = tid >> 4;         // rows 4ty..4ty+3
    const int lr  = tid >> 3;        // 0..31 (+32)
    const int lh4 = (tid & 7) << 2;
    const float* base = g_pp + (b << 8) * 512;

    ull acc[4][2];
    #pragma unroll
    for (int i = 0; i < 4; i++) { acc[i][0] = 0ull; acc[i][1] = 0ull; }

    for (int hc = 0; hc < 256; hc += 32) {
        __syncthreads();
        #pragma unroll
        for (int q = 0; q < 2; q++) {
            int r = lr + (q << 5);
            float4 v = *(const float4*)(base + (i0b + r) * 512 + hc + lh4);
            *(float2*)&adup[lh4 + 0][2 * r] = make_float2(v.x, v.x);
            *(float2*)&adup[lh4 + 1][2 * r] = make_float2(v.y, v.y);
            *(float2*)&adup[lh4 + 2][2 * r] = make_float2(v.z, v.z);
            *(float2*)&adup[lh4 + 3][2 * r] = make_float2(v.w, v.w);
            float4 u = *(const float4*)(base + (j0b + r) * 512 + 256 + hc + lh4);
            pcT[lh4 + 0][r] = u.x;
            pcT[lh4 + 1][r] = u.y;
            pcT[lh4 + 2][r] = u.z;
            pcT[lh4 + 3][r] = u.w;
        }
        if (tid < 32) { float w = W2[hc + tid]; wd[tid] = make_float2(w, w); }
        __syncthreads();
        #pragma unroll
        for (int h = 0; h < 32; h++) {
            float4 ap = *(float4*)&adup[h][8 * ty];      // {a0,a0,a1,a1}
            float4 aq = *(float4*)&adup[h][8 * ty + 4];  // {a2,a2,a3,a3}
            float4 cp = *(float4*)&pcT[h][4 * tx];       // {c0,c1,c2,c3}
            ull ad[4];
            ad[0] = ((ull*)&ap)[0]; ad[1] = ((ull*)&ap)[1];
            ad[2] = ((ull*)&aq)[0]; ad[3] = ((ull*)&aq)[1];
            ull c01 = ((ull*)&cp)[0];
            ull c23 = ((ull*)&cp)[1];
            ull w2p = *(ull*)&wd[h];
            #pragma unroll
            for (int i = 0; i < 4; i++) {
                ull v0, v1;
                ADD2(v0, ad[i], c01);
                ADD2(v1, ad[i], c23);
                float l0, h0, l1, h1;
                funpack(v0, l0, h0);
                funpack(v1, l1, h1);
                l0 = fmaxf(l0, 0.f); h0 = fmaxf(h0, 0.f);
                l1 = fmaxf(l1, 0.f); h1 = fmaxf(h1, 0.f);
                ull r0 = fpack(l0, h0);
                ull r1 = fpack(l1, h1);
                FMA2(acc[i][0], r0, w2p, acc[i][0]);
                FMA2(acc[i][1], r1, w2p, acc[i][1]);
            }
        }
    }
    float bb = b2[0];
    float lmax = -3.4e38f;
    #pragma unroll
    for (int i = 0; i < 4; i++) {
        float e0, e1, e2, e3;
        funpack(acc[i][0], e0, e1);
        funpack(acc[i][1], e2, e3);
        e0 += bb; e1 += bb; e2 += bb; e3 += bb;
        lmax = fmaxf(fmaxf(fmaxf(e0, e1), fmaxf(e2, e3)), lmax);
        *(float4*)(out_edge + (b << 16) + ((i0b + 4 * ty + i) << 8) + j0b + 4 * tx) =
            make_float4(e0, e1, e2, e3);
    }
    #pragma unroll
    for (int o = 16; o > 0; o >>= 1) lmax = fmaxf(lmax, __shfl_xor_sync(0xffffffffu, lmax, o));
    if ((tid & 31) == 0) redbuf[tid >> 5] = lmax;
    __syncthreads();
    if (tid == 0) {
        float m = redbuf[0];
        #pragma unroll
        for (int i = 1; i < 8; i++) m = fmaxf(m, redbuf[i]);
        atomicMax(&g_maxkey[b], encf(m));
    }
}

// ---------------- 3) exp + deterministic partial sums (float4) ----------------
__global__ __launch_bounds__(256) void exp_kernel(const float* __restrict__ edge)
{
    const int b = blockIdx.y;
    const int blk = blockIdx.x;     // 0..15
    const int tid = threadIdx.x;
    __shared__ float red[8];
    const float smax = 2.0f * decf(g_maxkey[b]);
    const float4* e4 = (const float4*)(edge + (b << 16) + (blk << 12));
    float4* o4 = (float4*)(g_e + (b << 16) + (blk << 12));
    float s = 0.f;
    #pragma unroll
    for (int t = 0; t < 4; t++) {
        float4 v = e4[t * 256 + tid];
        float4 r;
        r.x = __expf(fmaf(v.x, 2.0f, -smax));
        r.y = __expf(fmaf(v.y, 2.0f, -smax));
        r.z = __expf(fmaf(v.z, 2.0f, -smax));
        r.w = __expf(fmaf(v.w, 2.0f, -smax));
        o4[t * 256 + tid] = r;
        s += (r.x + r.y) + (r.z + r.w);
    }
    #pragma unroll
    for (int o = 16; o > 0; o >>= 1) s += __shfl_xor_sync(0xffffffffu, s, o);
    if ((tid & 31) == 0) red[tid >> 5] = s;
    __syncthreads();
    if (tid == 0) {
        float tot = 0.f;
        #pragma unroll
        for (int i = 0; i < 8; i++) tot += red[i];
        g_part[(b << 4) + blk] = tot;
    }
}

__global__ void denom_kernel() {
    const int b = blockIdx.x, tid = threadIdx.x;   // 32 threads
    float v = (tid < 16) ? g_part[(b << 4) + tid] : 0.f;
    #pragma unroll
    for (int o = 16; o > 0; o >>= 1) v += __shfl_xor_sync(0xffffffffu, v, o);
    if (tid == 0) g_inv_denom[b] = 1.0f / v;
}

__global__ void soft_kernel(float* __restrict__ out_soft) {
    int idx4 = blockIdx.x * 256 + threadIdx.x;
    float inv = g_inv_denom[idx4 >> 14];
    float4 v = ((const float4*)g_e)[idx4];
    ((float4*)out_soft)[idx4] = make_float4(v.x * inv, v.y * inv, v.z * inv, v.w * inv);
}

// ---------------- 4) radix select (warp-aggregated histograms) ----------------
__global__ __launch_bounds__(1024) void select_kernel(const float* __restrict__ soft)
{
    __shared__ unsigned hist[8][256];
    __shared__ unsigned sh_prefix;
    __shared__ int sh_rem;
    const int b = blockIdx.x;
    const int tid = threadIdx.x;
    const unsigned* keys = (const unsigned*)(soft + (b << 16));
    if (tid == 0) { sh_rem = Ksel; sh_prefix = 0u; }
    unsigned mask = 0u;
    for (int byte = 3; byte >= 0; byte--) {
        for (int i = tid; i < 2048; i += 1024) ((unsigned*)hist)[i] = 0u;
        __syncthreads();
        const unsigned prefix = sh_prefix;
        const int wg = (tid >> 5) & 7;
        const int sh = byte << 3;
        for (int t = tid; t < NN; t += 1024) {
            unsigned key = keys[t];
            bool act = (key & mask) == prefix;
            unsigned bucket = (key >> sh) & 255u;
            unsigned am = __ballot_sync(0xffffffffu, act);
            if (act) {
                unsigned peers = __match_any_sync(am, bucket);
                if ((unsigned)(__ffs(peers) - 1) == (tid & 31u))
                    atomicAdd(&hist[wg][bucket], __popc(peers));
            }
        }
        __syncthreads();
        if (tid < 256) {
            unsigned s = 0;
            #pragma unroll
            for (int c = 0; c < 8; c++) s += hist[c][tid];
            hist[0][tid] = s;
        }
        __syncthreads();
        if (tid == 0) {
            int rem = sh_rem;
            unsigned cum = 0;
            int sel = 0;
            for (int bb = 255; bb >= 0; bb--) {
                unsigned c = hist[0][bb];
                if (cum + c >= (unsigned)rem) { sel = bb; sh_rem = rem - (int)cum; break; }
                cum += c;
            }
            sh_prefix = prefix | ((unsigned)sel << sh);
        }
        __syncthreads();
        mask |= (255u << sh);
    }
    if (tid == 0) g_thr[b] = __uint_as_float(sh_prefix);
}

// ---------------- 5) masked sum + final write (float4) ----------------
__global__ __launch_bounds__(256) void cmask_sum_kernel(const float* __restrict__ soft)
{
    const int b = blockIdx.y, blk = blockIdx.x, tid = threadIdx.x;
    __shared__ float red[8];
    const float thr = g_thr[b];
    const float4* s4 = (const float4*)(soft + (b << 16) + (blk << 12));
    float s = 0.f;
    #pragma unroll
    for (int t = 0; t < 4; t++) {
        float4 v = s4[t * 256 + tid];
        if (v.x >= thr) s += v.x;
        if (v.y >= thr) s += v.y;
        if (v.z >= thr) s += v.z;
        if (v.w >= thr) s += v.w;
    }
    #pragma unroll
    for (int o = 16; o > 0; o >>= 1) s += __shfl_xor_sync(0xffffffffu, s, o);
    if ((tid & 31) == 0) red[tid >> 5] = s;
    __syncthreads();
    if (tid == 0) {
        float tot = 0.f;
        #pragma unroll
        for (int i = 0; i < 8; i++) tot += red[i];
        g_cpart[(b << 4) + blk] = tot;
    }
}

__global__ void csum_final_kernel() {
    const int b = blockIdx.x, tid = threadIdx.x;   // 32 threads
    float v = (tid < 16) ? g_cpart[(b << 4) + tid] : 0.f;
    #pragma unroll
    for (int o = 16; o > 0; o >>= 1) v += __shfl_xor_sync(0xffffffffu, v, o);
    if (tid == 0) g_inv_csum[b] = 1.0f / (v + 1e-12f);
}

__global__ void final_kernel(const float* __restrict__ soft,
                             float* __restrict__ out_causal, float* __restrict__ out_conf)
{
    int idx4 = blockIdx.x * 256 + threadIdx.x;
    int b = idx4 >> 14;
    float thr = g_thr[b];
    float inv = g_inv_csum[b];
    float4 v = ((const float4*)soft)[idx4];
    float4 c;
    c.x = (v.x >= thr) ? v.x * inv : 0.f;
    c.y = (v.y >= thr) ? v.y * inv : 0.f;
    c.z = (v.z >= thr) ? v.z * inv : 0.f;
    c.w = (v.w >= thr) ? v.w * inv : 0.f;
    ((float4*)out_causal)[idx4] = c;
    ((float4*)out_conf)[idx4] = make_float4(1.f - c.x, 1.f - c.y, 1.f - c.z, 1.f - c.w);
}

// ---------------- launch ----------------
extern "C" void kernel_launch(void* const* d_in, const int* in_sizes, int n_in,
                              void* d_out, int out_size)
{
    const float* x  = (const float*)d_in[0];
    const float* W1 = (const float*)d_in[1];
    const float* b1 = (const float*)d_in[2];
    const float* W2 = (const float*)d_in[3];
    const float* b2 = (const float*)d_in[4];
    float* out = (float*)d_out;
    float* out_causal = out;
    float* out_conf   = out + BNN;
    float* out_edge   = out + 2 * BNN;
    float* out_soft   = out + 3 * BNN;

    init_kernel<<<1, 32>>>();
    gemm_kernel<<<dim3(8, 16), 256>>>(x, W1, b1);
    edge_kernel<<<dim3(4, 4, Bsz), 256>>>(W2, b2, out_edge);
    exp_kernel<<<dim3(16, Bsz), 256>>>(out_edge);
    denom_kernel<<<Bsz, 32>>>();
    soft_kernel<<<512, 256>>>(out_soft);
    select_kernel<<<Bsz, 1024>>>(out_soft);
    cmask_sum_kernel<<<dim3(16, Bsz), 256>>>(out_soft);
    csum_final_kernel<<<Bsz, 32>>>();
    final_kernel<<<512, 256>>>(out_soft, out_causal, out_conf);
}

// round 4
// speedup vs baseline: 1.0795x; 1.0795x over previous
#include <cuda_runtime.h>

#define Bsz 8
#define FD 1024
#define NN 65536            // N*N per batch
#define BNN (Bsz*NN)        // 524288
#define Ksel 39321          // int(0.6 * 65536)
#define M_TOT 2048          // B*N

// ---------------- scratch ----------------
__device__ float    g_pp[M_TOT * 512];     // [m][0:256)=pr+b1, [256:512)=pc
__device__ float    g_e[BNN];              // unnormalized exp
__device__ unsigned g_maxkey[Bsz];
__device__ float    g_inv_denom[Bsz];
__device__ float    g_part[Bsz * 16];
__device__ float    g_thr[Bsz];
__device__ float    g_cpart[Bsz * 16];
__device__ float    g_inv_csum[Bsz];

// monotone float<->uint encoding (for atomicMax over possibly-negative floats)
__device__ __forceinline__ unsigned encf(float f) {
    unsigned u = __float_as_uint(f);
    return (u & 0x80000000u) ? ~u : (u | 0x80000000u);
}
__device__ __forceinline__ float decf(unsigned u) {
    unsigned v = (u & 0x80000000u) ? (u ^ 0x80000000u) : ~u;
    return __uint_as_float(v);
}

__global__ void init_kernel() {
    if (threadIdx.x < Bsz) g_maxkey[threadIdx.x] = 0u;
}

// ---------------- 1) GEMM: C[m][j] = sum_f x[m][f] * Bmat[j][f] ----------------
// Bmat[j][f] = W1[(j&255)][(j>>8)*1024 + f]; b1 folded into cols < 256.
// 128x64 tile, 256 threads, 8x4 per thread. Grid 8x16 = 128 CTAs = one wave.
__global__ __launch_bounds__(256) void gemm_kernel(
    const float* __restrict__ x, const float* __restrict__ W1, const float* __restrict__ b1)
{
    __shared__ float As[16][132];
    __shared__ float Bs[16][68];
    const int tid = threadIdx.x;
    const int j0 = blockIdx.x << 6;
    const int m0 = blockIdx.y << 7;
    const int tx = tid & 15;            // cols 4tx..4tx+3
    const int ty = tid >> 4;            // rows 8ty..8ty+7
    const int ar0 = tid >> 2;           // A slot row 0..63 (and +64)
    const int ac4 = (tid & 3) << 2;     // k-col group 0,4,8,12
    const int gj = j0 + (tid >> 2);     // B row
    const float* wrow = W1 + (gj & 255) * 2048 + (gj >> 8) * 1024;
    const float* arow0 = x + (m0 + ar0) * 1024 + ac4;
    const float* arow1 = arow0 + 64 * 1024;

    float acc[8][4] = {};

    float4 pa0 = *(const float4*)(arow0);
    float4 pa1 = *(const float4*)(arow1);
    float4 pb  = *(const float4*)(wrow + ac4);

    for (int k0 = 0; k0 < FD; k0 += 16) {
        __syncthreads();
        {
            float va[4] = {pa0.x, pa0.y, pa0.z, pa0.w};
            float vb[4] = {pa1.x, pa1.y, pa1.z, pa1.w};
            float vc[4] = {pb.x,  pb.y,  pb.z,  pb.w};
            #pragma unroll
            for (int d = 0; d < 4; d++) {
                As[ac4 + d][ar0]      = va[d];
                As[ac4 + d][64 + ar0] = vb[d];
                Bs[ac4 + d][tid >> 2] = vc[d];
            }
        }
        __syncthreads();
        if (k0 + 16 < FD) {
            pa0 = *(const float4*)(arow0 + k0 + 16);
            pa1 = *(const float4*)(arow1 + k0 + 16);
            pb  = *(const float4*)(wrow + k0 + 16 + ac4);
        }
        #pragma unroll
        for (int k = 0; k < 16; k++) {
            float a[8], bb[4];
            *(float4*)&a[0] = *(const float4*)&As[k][8 * ty];
            *(float4*)&a[4] = *(const float4*)&As[k][8 * ty + 4];
            *(float4*)&bb[0] = *(const float4*)&Bs[k][4 * tx];
            #pragma unroll
            for (int i = 0; i < 8; i++)
                #pragma unroll
                for (int j = 0; j < 4; j++)
                    acc[i][j] = fmaf(a[i], bb[j], acc[i][j]);
        }
    }
    float bias[4];
    #pragma unroll
    for (int jj = 0; jj < 4; jj++) {
        int col = j0 + 4 * tx + jj;
        bias[jj] = (col < 256) ? b1[col] : 0.f;
    }
    #pragma unroll
    for (int i = 0; i < 8; i++) {
        int m = m0 + 8 * ty + i;
        *(float4*)(g_pp + m * 512 + j0 + 4 * tx) =
            make_float4(acc[i][0] + bias[0], acc[i][1] + bias[1],
                        acc[i][2] + bias[2], acc[i][3] + bias[3]);
    }
}

// ---------------- 2) edge[b,i,j] = sum_h relu(pr[i,h]+pc[j,h])*w2[h] + b2 ----------------
__global__ __launch_bounds__(256) void edge_kernel(
    const float* __restrict__ W2, const float* __restrict__ b2, float* __restrict__ out_edge)
{
    __shared__ float prs[64][33];
    __shared__ float pcs[64][33];
    __shared__ float w2s[32];
    __shared__ float redbuf[8];
    const int b  = blockIdx.z;
    const int i0 = blockIdx.y << 6;
    const int j0 = blockIdx.x << 6;
    const int tid = threadIdx.x;
    const int tx = tid & 15, ty = tid >> 4;
    const float* base = g_pp + (b << 8) * 512;
    float acc[4][4] = {};
    for (int hc = 0; hc < 256; hc += 32) {
        __syncthreads();
        #pragma unroll
        for (int t = 0; t < 2; t++) {
            int idx = tid + (t << 8);            // 0..511 float4 slots
            int r = idx >> 3;
            int hv = (idx & 7) << 2;
            float4 v = *(const float4*)(base + (i0 + r) * 512 + hc + hv);
            prs[r][hv] = v.x; prs[r][hv + 1] = v.y; prs[r][hv + 2] = v.z; prs[r][hv + 3] = v.w;
            float4 u = *(const float4*)(base + (j0 + r) * 512 + 256 + hc + hv);
            pcs[r][hv] = u.x; pcs[r][hv + 1] = u.y; pcs[r][hv + 2] = u.z; pcs[r][hv + 3] = u.w;
        }
        if (tid < 32) w2s[tid] = W2[hc + tid];
        __syncthreads();
        #pragma unroll
        for (int h = 0; h < 32; h++) {
            float w = w2s[h];
            float a[4], c[4];
            #pragma unroll
            for (int t = 0; t < 4; t++) { a[t] = prs[(ty << 2) + t][h]; c[t] = pcs[(tx << 2) + t][h]; }
            #pragma unroll
            for (int i = 0; i < 4; i++)
                #pragma unroll
                for (int j = 0; j < 4; j++) {
                    float v = a[i] + c[j];
                    v = fmaxf(v, 0.f);
                    acc[i][j] = fmaf(v, w, acc[i][j]);
                }
        }
    }
    float bb = b2[0];
    float lmax = -3.4e38f;
    #pragma unroll
    for (int i = 0; i < 4; i++) {
        int ii = i0 + (ty << 2) + i;
        #pragma unroll
        for (int j = 0; j < 4; j++) {
            int jj = j0 + (tx << 2) + j;
            float e = acc[i][j] + bb;
            out_edge[(b << 16) + (ii << 8) + jj] = e;
            lmax = fmaxf(lmax, e);
        }
    }
    #pragma unroll
    for (int o = 16; o > 0; o >>= 1) lmax = fmaxf(lmax, __shfl_xor_sync(0xffffffffu, lmax, o));
    if ((tid & 31) == 0) redbuf[tid >> 5] = lmax;
    __syncthreads();
    if (tid == 0) {
        float m = redbuf[0];
        #pragma unroll
        for (int i = 1; i < 8; i++) m = fmaxf(m, redbuf[i]);
        atomicMax(&g_maxkey[b], encf(m));
    }
}

// ---------------- 3) exp + deterministic partial sums (float4) ----------------
__global__ __launch_bounds__(256) void exp_kernel(const float* __restrict__ edge)
{
    const int b = blockIdx.y;
    const int blk = blockIdx.x;     // 0..15
    const int tid = threadIdx.x;
    __shared__ float red[8];
    const float smax = 2.0f * decf(g_maxkey[b]);
    const float4* e4 = (const float4*)(edge + (b << 16) + (blk << 12));
    float4* o4 = (float4*)(g_e + (b << 16) + (blk << 12));
    float s = 0.f;
    #pragma unroll
    for (int t = 0; t < 4; t++) {
        float4 v = e4[t * 256 + tid];
        float4 r;
        r.x = __expf(fmaf(v.x, 2.0f, -smax));
        r.y = __expf(fmaf(v.y, 2.0f, -smax));
        r.z = __expf(fmaf(v.z, 2.0f, -smax));
        r.w = __expf(fmaf(v.w, 2.0f, -smax));
        o4[t * 256 + tid] = r;
        s += (r.x + r.y) + (r.z + r.w);
    }
    #pragma unroll
    for (int o = 16; o > 0; o >>= 1) s += __shfl_xor_sync(0xffffffffu, s, o);
    if ((tid & 31) == 0) red[tid >> 5] = s;
    __syncthreads();
    if (tid == 0) {
        float tot = 0.f;
        #pragma unroll
        for (int i = 0; i < 8; i++) tot += red[i];
        g_part[(b << 4) + blk] = tot;
    }
}

__global__ void denom_kernel() {
    const int b = blockIdx.x, tid = threadIdx.x;   // 32 threads
    float v = (tid < 16) ? g_part[(b << 4) + tid] : 0.f;
    #pragma unroll
    for (int o = 16; o > 0; o >>= 1) v += __shfl_xor_sync(0xffffffffu, v, o);
    if (tid == 0) g_inv_denom[b] = 1.0f / v;
}

__global__ void soft_kernel(float* __restrict__ out_soft) {
    int idx4 = blockIdx.x * 256 + threadIdx.x;
    float inv = g_inv_denom[idx4 >> 14];
    float4 v = ((const float4*)g_e)[idx4];
    ((float4*)out_soft)[idx4] = make_float4(v.x * inv, v.y * inv, v.z * inv, v.w * inv);
}

// ---------------- 4) radix select (warp-aggregated histograms) ----------------
__global__ __launch_bounds__(1024) void select_kernel(const float* __restrict__ soft)
{
    __shared__ unsigned hist[8][256];
    __shared__ unsigned sh_prefix;
    __shared__ int sh_rem;
    const int b = blockIdx.x;
    const int tid = threadIdx.x;
    const unsigned* keys = (const unsigned*)(soft + (b << 16));
    if (tid == 0) { sh_rem = Ksel; sh_prefix = 0u; }
    unsigned mask = 0u;
    for (int byte = 3; byte >= 0; byte--) {
        for (int i = tid; i < 2048; i += 1024) ((unsigned*)hist)[i] = 0u;
        __syncthreads();
        const unsigned prefix = sh_prefix;
        const int wg = (tid >> 5) & 7;
        const int sh = byte << 3;
        for (int t = tid; t < NN; t += 1024) {
            unsigned key = keys[t];
            bool act = (key & mask) == prefix;
            unsigned bucket = (key >> sh) & 255u;
            unsigned am = __ballot_sync(0xffffffffu, act);
            if (act) {
                unsigned peers = __match_any_sync(am, bucket);
                if ((unsigned)(__ffs(peers) - 1) == (tid & 31u))
                    atomicAdd(&hist[wg][bucket], __popc(peers));
            }
        }
        __syncthreads();
        if (tid < 256) {
            unsigned s = 0;
            #pragma unroll
            for (int c = 0; c < 8; c++) s += hist[c][tid];
            hist[0][tid] = s;
        }
        __syncthreads();
        if (tid == 0) {
            int rem = sh_rem;
            unsigned cum = 0;
            int sel = 0;
            for (int bb = 255; bb >= 0; bb--) {
                unsigned c = hist[0][bb];
                if (cum + c >= (unsigned)rem) { sel = bb; sh_rem = rem - (int)cum; break; }
                cum += c;
            }
            sh_prefix = prefix | ((unsigned)sel << sh);
        }
        __syncthreads();
        mask |= (255u << sh);
    }
    if (tid == 0) g_thr[b] = __uint_as_float(sh_prefix);
}

// ---------------- 5) masked sum + final write (float4) ----------------
__global__ __launch_bounds__(256) void cmask_sum_kernel(const float* __restrict__ soft)
{
    const int b = blockIdx.y, blk = blockIdx.x, tid = threadIdx.x;   // blk 0..15
    __shared__ float red[8];
    const float thr = g_thr[b];
    const float4* s4 = (const float4*)(soft + (b << 16) + (blk << 12));
    float s = 0.f;
    #pragma unroll
    for (int t = 0; t < 4; t++) {
        float4 v = s4[t * 256 + tid];
        if (v.x >= thr) s += v.x;
        if (v.y >= thr) s += v.y;
        if (v.z >= thr) s += v.z;
        if (v.w >= thr) s += v.w;
    }
    #pragma unroll
    for (int o = 16; o > 0; o >>= 1) s += __shfl_xor_sync(0xffffffffu, s, o);
    if ((tid & 31) == 0) red[tid >> 5] = s;
    __syncthreads();
    if (tid == 0) {
        float tot = 0.f;
        #pragma unroll
        for (int i = 0; i < 8; i++) tot += red[i];
        g_cpart[(b << 4) + blk] = tot;
    }
}

__global__ void csum_final_kernel() {
    const int b = blockIdx.x, tid = threadIdx.x;   // 32 threads
    float v = (tid < 16) ? g_cpart[(b << 4) + tid] : 0.f;
    #pragma unroll
    for (int o = 16; o > 0; o >>= 1) v += __shfl_xor_sync(0xffffffffu, v, o);
    if (tid == 0) g_inv_csum[b] = 1.0f / (v + 1e-12f);
}

__global__ void final_kernel(const float* __restrict__ soft,
                             float* __restrict__ out_causal, float* __restrict__ out_conf)
{
    int idx4 = blockIdx.x * 256 + threadIdx.x;
    int b = idx4 >> 14;
    float thr = g_thr[b];
    float inv = g_inv_csum[b];
    float4 v = ((const float4*)soft)[idx4];
    float4 c;
    c.x = (v.x >= thr) ? v.x * inv : 0.f;
    c.y = (v.y >= thr) ? v.y * inv : 0.f;
    c.z = (v.z >= thr) ? v.z * inv : 0.f;
    c.w = (v.w >= thr) ? v.w * inv : 0.f;
    ((float4*)out_causal)[idx4] = c;
    ((float4*)out_conf)[idx4] = make_float4(1.f - c.x, 1.f - c.y, 1.f - c.z, 1.f - c.w);
}

// ---------------- launch ----------------
extern "C" void kernel_launch(void* const* d_in, const int* in_sizes, int n_in,
                              void* d_out, int out_size)
{
    const float* x  = (const float*)d_in[0];
    const float* W1 = (const float*)d_in[1];
    const float* b1 = (const float*)d_in[2];
    const float* W2 = (const float*)d_in[3];
    const float* b2 = (const float*)d_in[4];
    float* out = (float*)d_out;
    float* out_causal = out;
    float* out_conf   = out + BNN;
    float* out_edge   = out + 2 * BNN;
    float* out_soft   = out + 3 * BNN;

    init_kernel<<<1, 32>>>();
    gemm_kernel<<<dim3(8, 16), 256>>>(x, W1, b1);
    edge_kernel<<<dim3(4, 4, Bsz), 256>>>(W2, b2, out_edge);
    exp_kernel<<<dim3(16, Bsz), 256>>>(out_edge);
    denom_kernel<<<Bsz, 32>>>();
    soft_kernel<<<512, 256>>>(out_soft);
    select_kernel<<<Bsz, 1024>>>(out_soft);
    cmask_sum_kernel<<<dim3(16, Bsz), 256>>>(out_soft);
    csum_final_kernel<<<Bsz, 32>>>();
    final_kernel<<<512, 256>>>(out_soft, out_causal, out_conf);
}